// round 1
// baseline (speedup 1.0000x reference)
#include <cuda_runtime.h>

#define T_LEN   8000
#define NTH     256
#define CHUNK   32
#define NWARPS  (NTH / 32)

__global__ __launch_bounds__(NTH) void pcen_kernel(
    const float* __restrict__ x,
    const float* __restrict__ log_s,
    const float* __restrict__ log_alpha,
    const float* __restrict__ log_delta,
    const float* __restrict__ log_r,
    float* __restrict__ out,
    int K)
{
    __shared__ float tile[T_LEN];
    __shared__ float wA[NWARPS], wB[NWARPS];
    __shared__ float warpPrefix[NWARPS];

    const int series = blockIdx.x;            // b*K + k  (C == 1)
    const int k      = series % K;
    const long long base = (long long)series * T_LEN;
    const int tid  = threadIdx.x;
    const int lane = tid & 31;
    const int warp = tid >> 5;

    // Per-series parameters (all per-K)
    const float s     = 1.0f / (1.0f + __expf(-log_s[k]));
    const float a     = 1.0f - s;
    const float alpha = __expf(log_alpha[k]);
    const float delta = __expf(log_delta[k]);
    const float r     = __expf(log_r[k]);
    const float dr    = __powf(delta, r);

    // ---- coalesced vectorized load of the whole series into smem ----
    {
        const float4* __restrict__ x4 = (const float4*)(x + base);
        float4* t4 = (float4*)tile;
        #pragma unroll 4
        for (int i = tid; i < T_LEN / 4; i += NTH)
            t4[i] = x4[i];
    }
    __syncthreads();

    // a^CHUNK via repeated squaring (CHUNK = 32 = 2^5)
    float a32 = a;
    #pragma unroll
    for (int q = 0; q < 5; q++) a32 *= a32;

    // ---- pass 1: per-thread chunk carry as an affine map f_out = A*f_in + B ----
    const int start = tid * CHUNK;
    float A, Bv;
    if (tid == 0) {
        // thread 0 embeds the init f[0] = x[0]; its map is constant: (A=0, B=c0)
        float f = tile[0];
        #pragma unroll
        for (int j = 1; j < CHUNK; j++)
            f = fmaf(a, f, s * tile[j]);
        A = 0.0f; Bv = f;
    } else if (start < T_LEN) {
        float f = 0.0f;
        #pragma unroll
        for (int j = 0; j < CHUNK; j++)
            f = fmaf(a, f, s * tile[start + j]);
        A = a32; Bv = f;
    } else {
        A = 1.0f; Bv = 0.0f;   // identity for idle threads 250..255
    }

    // ---- Kogge-Stone inclusive affine scan within warp ----
    #pragma unroll
    for (int d = 1; d < 32; d <<= 1) {
        float Au = __shfl_up_sync(0xffffffffu, A,  d);
        float Bu = __shfl_up_sync(0xffffffffu, Bv, d);
        if (lane >= d) { Bv = fmaf(A, Bu, Bv); A *= Au; }
    }
    if (lane == 31) { wA[warp] = A; wB[warp] = Bv; }
    __syncthreads();

    // cross-warp serial combine (8 pairs, one thread)
    if (tid == 0) {
        float p = 0.0f;
        #pragma unroll
        for (int w = 0; w < NWARPS; w++) {
            warpPrefix[w] = p;              // carry value entering warp w
            p = fmaf(wA[w], p, wB[w]);
        }
    }
    __syncthreads();

    // exclusive carry for this thread = filtered value at end of chunk tid-1
    float Au = __shfl_up_sync(0xffffffffu, A,  1);
    float Bu = __shfl_up_sync(0xffffffffu, Bv, 1);
    const float wp = warpPrefix[warp];
    float Eprev = (lane == 0) ? wp : fmaf(Au, wp, Bu);

    // ---- pass 2: recompute f exactly, apply PCEN pointwise, write into smem ----
    if (start < T_LEN) {
        float f = Eprev;
        #pragma unroll
        for (int j = 0; j < CHUNK; j++) {
            float xv = tile[start + j];
            if (tid == 0 && j == 0) f = xv;          // init frame
            else                    f = fmaf(a, f, s * xv);
            // x / (eps+f)^alpha  ==  x * exp2(-alpha * log2(eps+f))   (no division)
            float inv = exp2f(-alpha * __log2f(1e-6f + f));
            float o   = __powf(fmaf(xv, inv, delta), r) - dr;
            tile[start + j] = o;
        }
    }
    __syncthreads();

    // ---- coalesced vectorized store ----
    {
        float4* __restrict__ o4 = (float4*)(out + base);
        const float4* t4 = (const float4*)tile;
        #pragma unroll 4
        for (int i = tid; i < T_LEN / 4; i += NTH)
            o4[i] = t4[i];
    }
}

extern "C" void kernel_launch(void* const* d_in, const int* in_sizes, int n_in,
                              void* d_out, int out_size) {
    const float* x         = (const float*)d_in[0];
    const float* log_s     = (const float*)d_in[1];
    const float* log_alpha = (const float*)d_in[2];
    const float* log_delta = (const float*)d_in[3];
    const float* log_r     = (const float*)d_in[4];
    float* out = (float*)d_out;

    int K = in_sizes[1];                    // 128
    int nseries = in_sizes[0] / T_LEN;      // B*C*K = 4096

    pcen_kernel<<<nseries, NTH>>>(x, log_s, log_alpha, log_delta, log_r, out, K);
}

// round 2
// speedup vs baseline: 4.0501x; 4.0501x over previous
#include <cuda_runtime.h>

#define T_LEN   8000
#define NTH     256
#define CHUNK   32
#define NCHUNK  (T_LEN / CHUNK)     // 250
#define STRIDE  33                  // odd stride -> conflict-free transposed tile
#define NWARPS  (NTH / 32)

__global__ __launch_bounds__(NTH) void pcen_kernel(
    const float* __restrict__ x,
    const float* __restrict__ log_s,
    const float* __restrict__ log_alpha,
    const float* __restrict__ log_delta,
    const float* __restrict__ log_r,
    float* __restrict__ out,
    int K)
{
    __shared__ float tile[NCHUNK * STRIDE];   // 250*33*4 = 33000 B
    __shared__ float wA[NWARPS], wB[NWARPS];
    __shared__ float warpPrefix[NWARPS];

    const int series = blockIdx.x;            // b*K + k  (C == 1)
    const int k      = series % K;
    const long long base = (long long)series * T_LEN;
    const int tid  = threadIdx.x;
    const int lane = tid & 31;
    const int warp = tid >> 5;

    // Per-series parameters (all per-K)
    const float s     = 1.0f / (1.0f + __expf(-log_s[k]));
    const float a     = 1.0f - s;
    const float alpha = __expf(log_alpha[k]);
    const float delta = __expf(log_delta[k]);
    const float r     = __expf(log_r[k]);
    const float dr    = __powf(delta, r);

    // ---- stage: coalesced float4 LDG -> conflict-free scalar STS (chunk-major) ----
    {
        const float4* __restrict__ x4 = (const float4*)(x + base);
        #pragma unroll 4
        for (int i = tid; i < T_LEN / 4; i += NTH) {
            float4 v = x4[i];
            int t = i * 4;
            float* p = &tile[(t >> 5) * STRIDE + (t & 31)];  // j in {0,4,...,28}: no row crossing
            p[0] = v.x; p[1] = v.y; p[2] = v.z; p[3] = v.w;
        }
    }
    __syncthreads();

    // a^CHUNK via repeated squaring (CHUNK = 32 = 2^5)
    float a32 = a;
    #pragma unroll
    for (int q = 0; q < 5; q++) a32 *= a32;

    // ---- pass 1: per-thread chunk carry as an affine map f_out = A*f_in + B ----
    const float* __restrict__ myrow = &tile[tid * STRIDE];
    float A, Bv;
    if (tid == 0) {
        // thread 0 embeds the init f[0] = x[0]; its map is constant: (A=0, B=c0)
        float f = myrow[0];
        #pragma unroll
        for (int j = 1; j < CHUNK; j++)
            f = fmaf(a, f, s * myrow[j]);
        A = 0.0f; Bv = f;
    } else if (tid < NCHUNK) {
        float f = 0.0f;
        #pragma unroll
        for (int j = 0; j < CHUNK; j++)
            f = fmaf(a, f, s * myrow[j]);
        A = a32; Bv = f;
    } else {
        A = 1.0f; Bv = 0.0f;   // identity for idle threads 250..255
    }

    // ---- Kogge-Stone inclusive affine scan within warp ----
    #pragma unroll
    for (int d = 1; d < 32; d <<= 1) {
        float Au = __shfl_up_sync(0xffffffffu, A,  d);
        float Bu = __shfl_up_sync(0xffffffffu, Bv, d);
        if (lane >= d) { Bv = fmaf(A, Bu, Bv); A *= Au; }
    }
    if (lane == 31) { wA[warp] = A; wB[warp] = Bv; }
    __syncthreads();

    // cross-warp serial combine (8 pairs, one thread)
    if (tid == 0) {
        float p = 0.0f;
        #pragma unroll
        for (int w = 0; w < NWARPS; w++) {
            warpPrefix[w] = p;              // carry value entering warp w
            p = fmaf(wA[w], p, wB[w]);
        }
    }
    __syncthreads();

    // exclusive carry for this thread = filtered value at end of chunk tid-1
    float Au = __shfl_up_sync(0xffffffffu, A,  1);
    float Bu = __shfl_up_sync(0xffffffffu, Bv, 1);
    const float wp = warpPrefix[warp];
    float Eprev = (lane == 0) ? wp : fmaf(Au, wp, Bu);

    // ---- pass 2: recompute f exactly, apply PCEN pointwise, write back in place ----
    if (tid < NCHUNK) {
        float* __restrict__ row = &tile[tid * STRIDE];
        float f = Eprev;
        #pragma unroll
        for (int j = 0; j < CHUNK; j++) {
            float xv = row[j];
            if (tid == 0 && j == 0) f = xv;          // init frame
            else                    f = fmaf(a, f, s * xv);
            // x / (eps+f)^alpha  ==  x * exp2(-alpha * log2(eps+f))   (no division)
            float inv = exp2f(-alpha * __log2f(1e-6f + f));
            float o   = __powf(fmaf(xv, inv, delta), r) - dr;
            row[j] = o;
        }
    }
    __syncthreads();

    // ---- readout: conflict-free scalar LDS -> coalesced float4 STG ----
    {
        float4* __restrict__ o4 = (float4*)(out + base);
        #pragma unroll 4
        for (int i = tid; i < T_LEN / 4; i += NTH) {
            int t = i * 4;
            const float* p = &tile[(t >> 5) * STRIDE + (t & 31)];
            float4 v;
            v.x = p[0]; v.y = p[1]; v.z = p[2]; v.w = p[3];
            o4[i] = v;
        }
    }
}

extern "C" void kernel_launch(void* const* d_in, const int* in_sizes, int n_in,
                              void* d_out, int out_size) {
    const float* x         = (const float*)d_in[0];
    const float* log_s     = (const float*)d_in[1];
    const float* log_alpha = (const float*)d_in[2];
    const float* log_delta = (const float*)d_in[3];
    const float* log_r     = (const float*)d_in[4];
    float* out = (float*)d_out;

    int K = in_sizes[1];                    // 128
    int nseries = in_sizes[0] / T_LEN;      // B*C*K = 4096

    pcen_kernel<<<nseries, NTH>>>(x, log_s, log_alpha, log_delta, log_r, out, K);
}

// round 3
// speedup vs baseline: 4.1914x; 1.0349x over previous
#include <cuda_runtime.h>

#define T_LEN  8000
#define NTH    256
#define SEG    2000
#define NSEG   4
#define CHUNK  8
#define NCH    (SEG / CHUNK)     // 250 active threads
#define NWARPS (NTH / 32)
#define EPS    1e-6f

__global__ __launch_bounds__(NTH, 8) void pcen_kernel(
    const float* __restrict__ x,
    const float* __restrict__ log_s,
    const float* __restrict__ log_alpha,
    const float* __restrict__ log_delta,
    const float* __restrict__ log_r,
    float* __restrict__ out,
    int K)
{
    __shared__ float tile[2 * SEG];                 // double-buffered, 16 KB
    __shared__ float wA[NWARPS], wB[NWARPS], warpPrefix[NWARPS];

    const int series = blockIdx.x;                  // b*K + k  (C == 1)
    const int k      = series % K;
    const long long base = (long long)series * T_LEN;
    const int tid  = threadIdx.x;
    const int lane = tid & 31;
    const int warp = tid >> 5;

    // Per-series parameters (all per-K)
    const float s      = 1.0f / (1.0f + __expf(-log_s[k]));
    const float a      = 1.0f - s;
    const float nalpha = -__expf(log_alpha[k]);
    const float delta  = __expf(log_delta[k]);
    const float r      = __expf(log_r[k]);
    const float dr     = __powf(delta, r);
    const float inv_s  = 1.0f / s;
    float a8 = a; a8 *= a8; a8 *= a8; a8 *= a8;     // a^CHUNK

    float gcar = 0.0f;                              // carry (g-space), used by thread 0 only

    for (int seg = 0; seg < NSEG; seg++) {
        float* buf = tile + (seg & 1) * SEG;
        float4* b4 = (float4*)buf;

        // ---- stage: pure linear float4 copy (conflict-free STS.128) ----
        {
            const float4* __restrict__ x4 = (const float4*)(x + base + seg * SEG);
            #pragma unroll 2
            for (int i = tid; i < SEG / 4; i += NTH)
                b4[i] = x4[i];
        }
        __syncthreads();

        // ---- pass 1: per-thread 8-elt chunk -> affine map g_out = A*g_in + B ----
        float4 v0, v1;
        float A, Bv;
        const bool f0 = (seg == 0 && tid == 0);
        if (tid < NCH) {
            v0 = b4[tid * 2];
            v1 = b4[tid * 2 + 1];
            float g;
            if (f0) { g = v0.x * inv_s; A = 0.0f; }  // embed init f[0]=x[0] (g = x0/s)
            else    { g = v0.x;         A = a8;   }
            g = fmaf(a, g, v0.y); g = fmaf(a, g, v0.z); g = fmaf(a, g, v0.w);
            g = fmaf(a, g, v1.x); g = fmaf(a, g, v1.y); g = fmaf(a, g, v1.z);
            g = fmaf(a, g, v1.w);
            Bv = g;
        } else { A = 1.0f; Bv = 0.0f; }              // identity for threads 250..255

        // ---- Kogge-Stone inclusive affine scan within warp ----
        #pragma unroll
        for (int d = 1; d < 32; d <<= 1) {
            float Au = __shfl_up_sync(0xffffffffu, A,  d);
            float Bu = __shfl_up_sync(0xffffffffu, Bv, d);
            if (lane >= d) { Bv = fmaf(A, Bu, Bv); A *= Au; }
        }
        if (lane == 31) { wA[warp] = A; wB[warp] = Bv; }
        __syncthreads();

        // cross-warp serial combine; carry chained across segments via gcar
        if (tid == 0) {
            float p = gcar;
            #pragma unroll
            for (int w = 0; w < NWARPS; w++) {
                warpPrefix[w] = p;                   // g entering warp w
                p = fmaf(wA[w], p, wB[w]);
            }
            gcar = p;                                // g at end of this segment
        }
        __syncthreads();

        // exclusive carry entering this thread's chunk
        float Au = __shfl_up_sync(0xffffffffu, A,  1);
        float Bu = __shfl_up_sync(0xffffffffu, Bv, 1);
        const float wp = warpPrefix[warp];
        float E = (lane == 0) ? wp : fmaf(Au, wp, Bu);

        // ---- pass 2: recompute g exactly from registers, PCEN pointwise ----
        if (tid < NCH) {
            float g = E;

            #define PCEN_STEP(xv) do {                                   \
                float h   = fmaf(s, g, EPS);                             \
                float inv = exp2f(nalpha * __log2f(h));                  \
                float y   = fmaf((xv), inv, delta);                      \
                (xv)      = exp2f(r * __log2f(y)) - dr;                  \
            } while (0)

            if (f0) g = v0.x * inv_s; else g = fmaf(a, g, v0.x);
            PCEN_STEP(v0.x);
            g = fmaf(a, g, v0.y); PCEN_STEP(v0.y);
            g = fmaf(a, g, v0.z); PCEN_STEP(v0.z);
            g = fmaf(a, g, v0.w); PCEN_STEP(v0.w);
            g = fmaf(a, g, v1.x); PCEN_STEP(v1.x);
            g = fmaf(a, g, v1.y); PCEN_STEP(v1.y);
            g = fmaf(a, g, v1.z); PCEN_STEP(v1.z);
            g = fmaf(a, g, v1.w); PCEN_STEP(v1.w);
            #undef PCEN_STEP

            b4[tid * 2]     = v0;                    // outputs back in place (STS.128)
            b4[tid * 2 + 1] = v1;
        }
        __syncthreads();

        // ---- readout: pure linear float4 copy (conflict-free LDS.128 -> STG.128) ----
        {
            float4* __restrict__ o4 = (float4*)(out + base + seg * SEG);
            #pragma unroll 2
            for (int i = tid; i < SEG / 4; i += NTH)
                o4[i] = b4[i];
        }
        // no trailing barrier needed: next segment writes the other buffer, and
        // its post-stage barrier orders this readout before buffer reuse.
    }
}

extern "C" void kernel_launch(void* const* d_in, const int* in_sizes, int n_in,
                              void* d_out, int out_size) {
    const float* x         = (const float*)d_in[0];
    const float* log_s     = (const float*)d_in[1];
    const float* log_alpha = (const float*)d_in[2];
    const float* log_delta = (const float*)d_in[3];
    const float* log_r     = (const float*)d_in[4];
    float* out = (float*)d_out;

    int K = in_sizes[1];                    // 128
    int nseries = in_sizes[0] / T_LEN;      // B*C*K = 4096

    pcen_kernel<<<nseries, NTH>>>(x, log_s, log_alpha, log_delta, log_r, out, K);
}

// round 4
// speedup vs baseline: 4.8101x; 1.1476x over previous
#include <cuda_runtime.h>

#define T_LEN  8000
#define NTH    256
#define SEG    2000
#define NSEG   4
#define CHUNK  8
#define NCH    (SEG / CHUNK)     // 250 active threads
#define NWARPS (NTH / 32)
#define EPS    1e-6f

__device__ __forceinline__ float flg2(float v) {
    float r; asm("lg2.approx.ftz.f32 %0, %1;" : "=f"(r) : "f"(v)); return r;
}
__device__ __forceinline__ float fex2(float v) {
    float r; asm("ex2.approx.ftz.f32 %0, %1;" : "=f"(r) : "f"(v)); return r;
}

__global__ __launch_bounds__(NTH, 6) void pcen_kernel(
    const float* __restrict__ x,
    const float* __restrict__ log_s,
    const float* __restrict__ log_alpha,
    const float* __restrict__ log_delta,
    const float* __restrict__ log_r,
    float* __restrict__ out,
    int K)
{
    // double-buffered warp aggregates (A,B per warp) — only smem in the kernel
    __shared__ float sA[2][NWARPS], sB[2][NWARPS];

    const int series = blockIdx.x;                  // b*K + k  (C == 1)
    const int k      = series % K;
    const long long base = (long long)series * T_LEN;
    const int tid  = threadIdx.x;
    const int lane = tid & 31;
    const int warp = tid >> 5;

    // Per-series parameters (all per-K)
    const float s      = 1.0f / (1.0f + __expf(-log_s[k]));
    const float a      = 1.0f - s;
    const float nalpha = -__expf(log_alpha[k]);
    const float delta  = __expf(log_delta[k]);
    const float r      = __expf(log_r[k]);
    const float dr     = fex2(r * flg2(delta));     // delta^r
    const float inv_s  = 1.0f / s;
    float a8 = a; a8 *= a8; a8 *= a8; a8 *= a8;     // a^CHUNK

    float gcar = 0.0f;                              // segment carry in g-space (all threads)

    for (int seg = 0; seg < NSEG; seg++) {
        const int par = seg & 1;
        const long long sb = base + (long long)seg * SEG;

        // ---- load: 8 contiguous elements per thread, straight to registers ----
        float4 v0, v1;
        float A, Bv;
        const bool f0 = (seg == 0 && tid == 0);
        if (tid < NCH) {
            const float4* __restrict__ p4 = (const float4*)(x + sb + tid * CHUNK);
            v0 = p4[0];
            v1 = p4[1];
            // pass 1: chunk -> affine map  g_out = A*g_in + B   (g = f/s space)
            float g;
            if (f0) { g = v0.x * inv_s; A = 0.0f; }  // embed init f[0]=x[0]
            else    { g = v0.x;         A = a8;   }
            g = fmaf(a, g, v0.y); g = fmaf(a, g, v0.z); g = fmaf(a, g, v0.w);
            g = fmaf(a, g, v1.x); g = fmaf(a, g, v1.y); g = fmaf(a, g, v1.z);
            g = fmaf(a, g, v1.w);
            Bv = g;
        } else { A = 1.0f; Bv = 0.0f; }              // identity for threads 250..255

        // ---- Kogge-Stone inclusive affine scan within warp ----
        #pragma unroll
        for (int d = 1; d < 32; d <<= 1) {
            float Au = __shfl_up_sync(0xffffffffu, A,  d);
            float Bu = __shfl_up_sync(0xffffffffu, Bv, d);
            if (lane >= d) { Bv = fmaf(A, Bu, Bv); A *= Au; }
        }
        if (lane == 31) { sA[par][warp] = A; sB[par][warp] = Bv; }
        __syncthreads();     // the ONLY barrier per segment

        // ---- every thread folds the 8 warp aggregates (redundant, register-serial) ----
        float myP = gcar;    // g entering my warp
        {
            float p = gcar;
            #pragma unroll
            for (int w = 0; w < NWARPS; w++) {
                if (w == warp) myP = p;
                p = fmaf(sA[par][w], p, sB[par][w]);
            }
            gcar = p;        // g at segment end — identical in all threads
        }

        // exclusive carry entering this thread's chunk
        float Au = __shfl_up_sync(0xffffffffu, A,  1);
        float Bu = __shfl_up_sync(0xffffffffu, Bv, 1);
        float E  = (lane == 0) ? myP : fmaf(Au, myP, Bu);

        // ---- pass 2: recompute g exactly, PCEN pointwise, store straight out ----
        if (tid < NCH) {
            float g = E;

            #define PCEN_STEP(xv) do {                                   \
                float h   = fmaf(s, g, EPS);                             \
                float inv = fex2(nalpha * flg2(h));                      \
                float y   = fmaf((xv), inv, delta);                      \
                (xv)      = fex2(r * flg2(y)) - dr;                      \
            } while (0)

            if (f0) g = v0.x * inv_s; else g = fmaf(a, g, v0.x);
            PCEN_STEP(v0.x);
            g = fmaf(a, g, v0.y); PCEN_STEP(v0.y);
            g = fmaf(a, g, v0.z); PCEN_STEP(v0.z);
            g = fmaf(a, g, v0.w); PCEN_STEP(v0.w);
            g = fmaf(a, g, v1.x); PCEN_STEP(v1.x);
            g = fmaf(a, g, v1.y); PCEN_STEP(v1.y);
            g = fmaf(a, g, v1.z); PCEN_STEP(v1.z);
            g = fmaf(a, g, v1.w); PCEN_STEP(v1.w);
            #undef PCEN_STEP

            float4* __restrict__ o4 = (float4*)(out + sb + tid * CHUNK);
            o4[0] = v0;
            o4[1] = v1;
        }
        // next segment uses the other aggregate buffer; its barrier orders reuse
    }
}

extern "C" void kernel_launch(void* const* d_in, const int* in_sizes, int n_in,
                              void* d_out, int out_size) {
    const float* x         = (const float*)d_in[0];
    const float* log_s     = (const float*)d_in[1];
    const float* log_alpha = (const float*)d_in[2];
    const float* log_delta = (const float*)d_in[3];
    const float* log_r     = (const float*)d_in[4];
    float* out = (float*)d_out;

    int K = in_sizes[1];                    // 128
    int nseries = in_sizes[0] / T_LEN;      // B*C*K = 4096

    pcen_kernel<<<nseries, NTH>>>(x, log_s, log_alpha, log_delta, log_r, out, K);
}

// round 5
// speedup vs baseline: 5.0438x; 1.0486x over previous
#include <cuda_runtime.h>

#define T_LEN   8000
#define NTH     256
#define WPB     (NTH / 32)         // warps (series) per block
#define TILE    256                // elements per warp-iteration (8 per lane)
#define NFULL   31                 // 31*256 = 7936
#define TAILOFF 7936               // remaining 64 elements -> 2 per lane
#define EPS     1e-6f

__device__ __forceinline__ float flg2(float v) {
    float r; asm("lg2.approx.ftz.f32 %0, %1;" : "=f"(r) : "f"(v)); return r;
}
__device__ __forceinline__ float fex2(float v) {
    float r; asm("ex2.approx.ftz.f32 %0, %1;" : "=f"(r) : "f"(v)); return r;
}

__global__ __launch_bounds__(NTH) void pcen_kernel(
    const float* __restrict__ x,
    const float* __restrict__ log_s,
    const float* __restrict__ log_alpha,
    const float* __restrict__ log_delta,
    const float* __restrict__ log_r,
    float* __restrict__ out,
    int K)
{
    const int lane   = threadIdx.x & 31;
    const int series = blockIdx.x * WPB + (threadIdx.x >> 5);   // one warp per series
    const int k      = series % K;
    const long long base = (long long)series * T_LEN;

    // Per-series parameters (all per-K)
    const float s      = 1.0f / (1.0f + __expf(-log_s[k]));
    const float a      = 1.0f - s;
    const float nalpha = -__expf(log_alpha[k]);
    const float delta  = __expf(log_delta[k]);
    const float r      = __expf(log_r[k]);
    const float dr     = fex2(r * flg2(delta));     // delta^r
    const float inv_s  = 1.0f / s;
    const float a2     = a * a;
    float a8 = a2; a8 *= a8; a8 *= a8;              // a^8

    const float4* __restrict__ xp = (const float4*)(x + base);
    float4*       __restrict__ op = (float4*)(out + base);

    float gcar = 0.0f;                              // carry in g-space (uniform per warp)

    #define PCEN_STEP(xv) do {                                   \
        float h_   = fmaf(s, g, EPS);                            \
        float inv_ = fex2(nalpha * flg2(h_));                    \
        float y_   = fmaf((xv), inv_, delta);                    \
        (xv)       = fex2(r * flg2(y_)) - dr;                    \
    } while (0)

    // prefetch tile 0
    float4 v0 = xp[lane * 2];
    float4 v1 = xp[lane * 2 + 1];

    #pragma unroll 1
    for (int it = 0; it < NFULL; it++) {
        // ---- prefetch next tile while this one computes ----
        float4 n0, n1;
        if (it + 1 < NFULL) {
            n0 = xp[(it + 1) * (TILE / 4) + lane * 2];
            n1 = xp[(it + 1) * (TILE / 4) + lane * 2 + 1];
        }

        // ---- pass 1: 8-elt chunk -> affine map  g_out = A*g_in + B ----
        const bool f0 = (it == 0 && lane == 0);
        float A, Bv;
        {
            float g;
            if (f0) { g = v0.x * inv_s; A = 0.0f; }  // embed init f[0] = x[0]
            else    { g = v0.x;         A = a8;   }
            g = fmaf(a, g, v0.y); g = fmaf(a, g, v0.z); g = fmaf(a, g, v0.w);
            g = fmaf(a, g, v1.x); g = fmaf(a, g, v1.y); g = fmaf(a, g, v1.z);
            g = fmaf(a, g, v1.w);
            Bv = g;
        }

        // ---- Kogge-Stone inclusive affine scan (warp-wide, shuffles only) ----
        #pragma unroll
        for (int d = 1; d < 32; d <<= 1) {
            float Au = __shfl_up_sync(0xffffffffu, A,  d);
            float Bu = __shfl_up_sync(0xffffffffu, Bv, d);
            if (lane >= d) { Bv = fmaf(A, Bu, Bv); A *= Au; }
        }

        // exclusive carry entering this lane's chunk; advance warp carry
        float Ap = __shfl_up_sync(0xffffffffu, A,  1);
        float Bp = __shfl_up_sync(0xffffffffu, Bv, 1);
        float E  = (lane == 0) ? gcar : fmaf(Ap, gcar, Bp);
        float A31 = __shfl_sync(0xffffffffu, A,  31);
        float B31 = __shfl_sync(0xffffffffu, Bv, 31);
        gcar = fmaf(A31, gcar, B31);

        // ---- pass 2: recompute g exactly, PCEN pointwise, store ----
        {
            float g = E;
            if (f0) g = v0.x * inv_s; else g = fmaf(a, g, v0.x);
            PCEN_STEP(v0.x);
            g = fmaf(a, g, v0.y); PCEN_STEP(v0.y);
            g = fmaf(a, g, v0.z); PCEN_STEP(v0.z);
            g = fmaf(a, g, v0.w); PCEN_STEP(v0.w);
            g = fmaf(a, g, v1.x); PCEN_STEP(v1.x);
            g = fmaf(a, g, v1.y); PCEN_STEP(v1.y);
            g = fmaf(a, g, v1.z); PCEN_STEP(v1.z);
            g = fmaf(a, g, v1.w); PCEN_STEP(v1.w);
        }
        op[it * (TILE / 4) + lane * 2]     = v0;
        op[it * (TILE / 4) + lane * 2 + 1] = v1;

        v0 = n0; v1 = n1;
    }

    // ---- tail: 64 elements, 2 per lane ----
    {
        float2 w = *(const float2*)(x + base + TAILOFF + lane * 2);
        float A = a2, Bv;
        {
            float g = w.x;
            g = fmaf(a, g, w.y);
            Bv = g;
        }
        #pragma unroll
        for (int d = 1; d < 32; d <<= 1) {
            float Au = __shfl_up_sync(0xffffffffu, A,  d);
            float Bu = __shfl_up_sync(0xffffffffu, Bv, d);
            if (lane >= d) { Bv = fmaf(A, Bu, Bv); A *= Au; }
        }
        float Ap = __shfl_up_sync(0xffffffffu, A,  1);
        float Bp = __shfl_up_sync(0xffffffffu, Bv, 1);
        float E  = (lane == 0) ? gcar : fmaf(Ap, gcar, Bp);

        float g = fmaf(a, E, w.x);
        PCEN_STEP(w.x);
        g = fmaf(a, g, w.y); PCEN_STEP(w.y);

        *(float2*)(out + base + TAILOFF + lane * 2) = w;
    }
    #undef PCEN_STEP
}

extern "C" void kernel_launch(void* const* d_in, const int* in_sizes, int n_in,
                              void* d_out, int out_size) {
    const float* x         = (const float*)d_in[0];
    const float* log_s     = (const float*)d_in[1];
    const float* log_alpha = (const float*)d_in[2];
    const float* log_delta = (const float*)d_in[3];
    const float* log_r     = (const float*)d_in[4];
    float* out = (float*)d_out;

    int K = in_sizes[1];                    // 128
    int nseries = in_sizes[0] / T_LEN;      // B*C*K = 4096

    pcen_kernel<<<nseries / WPB, NTH>>>(x, log_s, log_alpha, log_delta, log_r, out, K);
}

// round 6
// speedup vs baseline: 5.2748x; 1.0458x over previous
#include <cuda_runtime.h>

#define T_LEN   8000
#define TILE    256                // elements per warp-iteration (8 per lane)
#define NFULL   31                 // 31*256 = 7936
#define TAILOFF 7936               // remaining 64 elements -> 2 per lane
#define EPS     1e-6f

__device__ __forceinline__ float flg2(float v) {
    float r; asm("lg2.approx.ftz.f32 %0, %1;" : "=f"(r) : "f"(v)); return r;
}
__device__ __forceinline__ float fex2(float v) {
    float r; asm("ex2.approx.ftz.f32 %0, %1;" : "=f"(r) : "f"(v)); return r;
}

__global__ __launch_bounds__(32) void pcen_kernel(
    const float* __restrict__ x,
    const float* __restrict__ log_s,
    const float* __restrict__ log_alpha,
    const float* __restrict__ log_delta,
    const float* __restrict__ log_r,
    float* __restrict__ out,
    int K)
{
    const int lane   = threadIdx.x;                 // 1 warp per block
    const int series = blockIdx.x;                  // one warp per series
    const int k      = series % K;
    const long long base = (long long)series * T_LEN;

    // Per-series parameters (all per-K)
    const float s      = 1.0f / (1.0f + __expf(-log_s[k]));
    const float a      = 1.0f - s;
    const float nalpha = -__expf(log_alpha[k]);
    const float delta  = __expf(log_delta[k]);
    const float r      = __expf(log_r[k]);
    const float dr     = fex2(r * flg2(delta));     // delta^r
    const float inv_s  = 1.0f / s;
    const float a2     = a * a;
    float a8 = a2; a8 *= a8; a8 *= a8;              // a^8

    const float4* __restrict__ xp = (const float4*)(x + base);
    float4*       __restrict__ op = (float4*)(out + base);

    float gcar = 0.0f;                              // carry in g-space (uniform per warp)

    #define PCEN_STEP(xv) do {                                   \
        float h_   = fmaf(s, g, EPS);                            \
        float inv_ = fex2(nalpha * flg2(h_));                    \
        float y_   = fmaf((xv), inv_, delta);                    \
        (xv)       = fex2(r * flg2(y_)) - dr;                    \
    } while (0)

    // prefetch tiles 0 and 1 (depth-2 pipeline: 4 LDG.128 in flight)
    float4 v0 = xp[lane * 2];
    float4 v1 = xp[lane * 2 + 1];
    float4 n0 = xp[(TILE / 4) + lane * 2];
    float4 n1 = xp[(TILE / 4) + lane * 2 + 1];

    #pragma unroll 1
    for (int it = 0; it < NFULL; it++) {
        // ---- prefetch tile it+2 while tile it computes ----
        float4 m0, m1;
        if (it + 2 < NFULL) {
            m0 = xp[(it + 2) * (TILE / 4) + lane * 2];
            m1 = xp[(it + 2) * (TILE / 4) + lane * 2 + 1];
        }

        // ---- pass 1: 8-elt chunk -> affine map  g_out = A*g_in + B ----
        const bool f0 = (it == 0 && lane == 0);
        float A, Bv;
        {
            float g;
            if (f0) { g = v0.x * inv_s; A = 0.0f; }  // embed init f[0] = x[0]
            else    { g = v0.x;         A = a8;   }
            g = fmaf(a, g, v0.y); g = fmaf(a, g, v0.z); g = fmaf(a, g, v0.w);
            g = fmaf(a, g, v1.x); g = fmaf(a, g, v1.y); g = fmaf(a, g, v1.z);
            g = fmaf(a, g, v1.w);
            Bv = g;
        }

        // ---- Kogge-Stone inclusive affine scan (warp-wide, shuffles only) ----
        #pragma unroll
        for (int d = 1; d < 32; d <<= 1) {
            float Au = __shfl_up_sync(0xffffffffu, A,  d);
            float Bu = __shfl_up_sync(0xffffffffu, Bv, d);
            if (lane >= d) { Bv = fmaf(A, Bu, Bv); A *= Au; }
        }

        // exclusive carry entering this lane's chunk; advance warp carry
        float Ap = __shfl_up_sync(0xffffffffu, A,  1);
        float Bp = __shfl_up_sync(0xffffffffu, Bv, 1);
        float E  = (lane == 0) ? gcar : fmaf(Ap, gcar, Bp);
        float A31 = __shfl_sync(0xffffffffu, A,  31);
        float B31 = __shfl_sync(0xffffffffu, Bv, 31);
        gcar = fmaf(A31, gcar, B31);

        // ---- pass 2: recompute g exactly, PCEN pointwise, store ----
        {
            float g = E;
            if (f0) g = v0.x * inv_s; else g = fmaf(a, g, v0.x);
            PCEN_STEP(v0.x);
            g = fmaf(a, g, v0.y); PCEN_STEP(v0.y);
            g = fmaf(a, g, v0.z); PCEN_STEP(v0.z);
            g = fmaf(a, g, v0.w); PCEN_STEP(v0.w);
            g = fmaf(a, g, v1.x); PCEN_STEP(v1.x);
            g = fmaf(a, g, v1.y); PCEN_STEP(v1.y);
            g = fmaf(a, g, v1.z); PCEN_STEP(v1.z);
            g = fmaf(a, g, v1.w); PCEN_STEP(v1.w);
        }
        op[it * (TILE / 4) + lane * 2]     = v0;
        op[it * (TILE / 4) + lane * 2 + 1] = v1;

        v0 = n0; v1 = n1;
        n0 = m0; n1 = m1;
    }

    // ---- tail: 64 elements, 2 per lane ----
    {
        float2 w = *(const float2*)(x + base + TAILOFF + lane * 2);
        float A = a2, Bv;
        {
            float g = w.x;
            g = fmaf(a, g, w.y);
            Bv = g;
        }
        #pragma unroll
        for (int d = 1; d < 32; d <<= 1) {
            float Au = __shfl_up_sync(0xffffffffu, A,  d);
            float Bu = __shfl_up_sync(0xffffffffu, Bv, d);
            if (lane >= d) { Bv = fmaf(A, Bu, Bv); A *= Au; }
        }
        float Ap = __shfl_up_sync(0xffffffffu, A,  1);
        float Bp = __shfl_up_sync(0xffffffffu, Bv, 1);
        float E  = (lane == 0) ? gcar : fmaf(Ap, gcar, Bp);

        float g = fmaf(a, E, w.x);
        PCEN_STEP(w.x);
        g = fmaf(a, g, w.y); PCEN_STEP(w.y);

        *(float2*)(out + base + TAILOFF + lane * 2) = w;
    }
    #undef PCEN_STEP
}

extern "C" void kernel_launch(void* const* d_in, const int* in_sizes, int n_in,
                              void* d_out, int out_size) {
    const float* x         = (const float*)d_in[0];
    const float* log_s     = (const float*)d_in[1];
    const float* log_alpha = (const float*)d_in[2];
    const float* log_delta = (const float*)d_in[3];
    const float* log_r     = (const float*)d_in[4];
    float* out = (float*)d_out;

    int K = in_sizes[1];                    // 128
    int nseries = in_sizes[0] / T_LEN;      // B*C*K = 4096

    pcen_kernel<<<nseries, 32>>>(x, log_s, log_alpha, log_delta, log_r, out, K);
}